// round 7
// baseline (speedup 1.0000x reference)
#include <cuda_runtime.h>
#include <math.h>

#define Bsz 16384
#define Dn  20
#define NSTEP 100

// ---------------- device scratch (no allocation allowed) ----------------
__device__ float    g_S[Bsz * Dn];   // final P-measure prices
__device__ float    g_xpre[Bsz];     // wealth after loop (pre-rescale)
__device__ float    g_dacc[Bsz];     // turnover sum
__device__ float    g_xfin[Bsz];     // final wealth
__device__ float    g_stats[48];     // [0..19]=C0, [20..39]=P0, [40]=rescale, [42]=loss6
__device__ float    g_part5[128];    // per-block partials of C_T[:,0]
__device__ unsigned g_keys[Bsz];     // sortable keys of g_xfin

// ---------------- packed fp32x2 helpers ----------------
__device__ __forceinline__ unsigned long long pack2(float lo, float hi) {
    unsigned long long r; asm("mov.b64 %0,{%1,%2};" : "=l"(r) : "f"(lo), "f"(hi)); return r;
}
__device__ __forceinline__ void unpack2(unsigned long long v, float &lo, float &hi) {
    asm("mov.b64 {%0,%1},%2;" : "=f"(lo), "=f"(hi) : "l"(v));
}
__device__ __forceinline__ unsigned long long ffma2(unsigned long long a,
                                                    unsigned long long b,
                                                    unsigned long long c) {
    unsigned long long d;
    asm("fma.rn.f32x2 %0,%1,%2,%3;" : "=l"(d) : "l"(a), "l"(b), "l"(c));
    return d;
}

// 64x64 dense + bias + relu + (prescaled BN gamma) + beta, in place on h[64].
// W row-major [k][j] in shared; bias/g/bb in shared.
__device__ __forceinline__ void dense64(float *h, const float *W, const float *bias,
                                        const float *g, const float *bb) {
    unsigned long long acc[32];
    const ulonglong2 *b4 = (const ulonglong2 *)bias;
#pragma unroll
    for (int p = 0; p < 16; p++) { ulonglong2 t = b4[p]; acc[2*p] = t.x; acc[2*p+1] = t.y; }
#pragma unroll
    for (int k = 0; k < 64; k++) {
        unsigned long long hk = pack2(h[k], h[k]);
        const ulonglong2 *w = (const ulonglong2 *)(W + (k << 6));
#pragma unroll
        for (int p = 0; p < 16; p++) {
            ulonglong2 wv = w[p];
            acc[2*p]   = ffma2(hk, wv.x, acc[2*p]);
            acc[2*p+1] = ffma2(hk, wv.y, acc[2*p+1]);
        }
    }
#pragma unroll
    for (int j = 0; j < 32; j++) {
        float lo, hi; unpack2(acc[j], lo, hi);
        h[2*j]   = fmaf(fmaxf(lo, 0.f), g[2*j],   bb[2*j]);
        h[2*j+1] = fmaf(fmaxf(hi, 0.f), g[2*j+1], bb[2*j+1]);
    }
}

// ---------------- K1: SDE + policy MLP simulation, one thread per path ----------------
__global__ void __launch_bounds__(128)
k_sim(const float *__restrict__ x_in,  const float *__restrict__ S0,
      const float *__restrict__ dW,    const float *__restrict__ u0W,
      const float *__restrict__ u0b,   const float *__restrict__ uWin,
      const float *__restrict__ uWh,   const float *__restrict__ ubh,
      const float *__restrict__ bng,   const float *__restrict__ bnb,
      const float *__restrict__ uWout, const float *__restrict__ ubout)
{
    __shared__ __align__(16) float sm[10132];
    float *sW1 = sm,        *sW2 = sm + 4096, *sWo = sm + 8192;
    float *sWi = sm + 9472, *sB0 = sm + 9536, *sG0 = sm + 9600, *sBB0 = sm + 9664;
    float *sB1 = sm + 9728, *sG1 = sm + 9792, *sBB1 = sm + 9856;
    float *sB2 = sm + 9920, *sG2 = sm + 9984, *sBB2 = sm + 10048, *sBo = sm + 10112;

    const int tid = threadIdx.x;
    const int b   = blockIdx.x * 128 + tid;

    const float sqh = sqrtf(0.01f);
    const float SIG = 0.2f;
    const float cS  = (0.06f - 0.5f * 0.2f * 0.2f) * 0.01f;   // P log-drift per step
    const float rh  = 0.02f * 0.01f;
    const float muh = 0.06f * 0.01f;
    const float inv_bn = 1.0f / sqrtf(1.0f + 1e-3f);

    float x = x_in[b];
    float S[Dn], Nm1[Dn], alpha[Dn];
    float dacc = 0.f;
#pragma unroll
    for (int d = 0; d < Dn; d++) {
        S[d] = S0[b * Dn + d];
        Nm1[d] = 0.f;
        alpha[d] = fmaf(x, u0W[d], u0b[d]);
    }

#pragma unroll 1
    for (int n = 1; n <= NSTEP; n++) {
        const float4 *dwp = (const float4 *)(dW + (size_t)(n - 1) * Bsz * Dn + (size_t)b * Dn);
        float4 w0 = dwp[0], w1 = dwp[1], w2 = dwp[2], w3 = dwp[3], w4 = dwp[4];
        float dv[Dn] = { w0.x, w0.y, w0.z, w0.w, w1.x, w1.y, w1.z, w1.w,
                         w2.x, w2.y, w2.z, w2.w, w3.x, w3.y, w3.z, w3.w,
                         w4.x, w4.y, w4.z, w4.w };
        float su = 0.f, sus = 0.f;
#pragma unroll
        for (int d = 0; d < Dn; d++) {
            float u  = alpha[d];
            float Np = __fdividef(u, S[d]);
            if (n > 1) dacc += fabsf(Np - Nm1[d]);
            Nm1[d] = Np;
            float sdw = SIG * (sqh * dv[d]);
            su  += u;
            sus  = fmaf(u, muh + sdw, sus);
            S[d] *= __expf(cS + sdw);
        }
        x = fmaf(x - su, rh, x) + sus;

        if ((n % 10) == 0 && n < NSTEP) {         // n = 10..90, uniform across block
            const int idx = n / 10 - 1;
            __syncthreads();
            {
                const float *ws = uWh + (size_t)idx * 2 * 64 * 64;
                for (int i = tid; i < 4096; i += 128) { sW1[i] = ws[i]; sW2[i] = ws[4096 + i]; }
                const float *wo = uWout + (size_t)idx * 64 * Dn;
                for (int i = tid; i < 64 * Dn; i += 128) sWo[i] = wo[i];
                const float *wi = uWin + idx * 64;
                const float *bh = ubh + idx * 192;
                const float *gg = bng + idx * 192;
                const float *bv = bnb + idx * 192;
                for (int i = tid; i < 64; i += 128) {
                    sWi[i] = wi[i];
                    sB0[i] = bh[i];            sB1[i] = bh[64 + i];            sB2[i] = bh[128 + i];
                    sG0[i] = inv_bn * gg[i];   sG1[i] = inv_bn * gg[64 + i];   sG2[i] = inv_bn * gg[128 + i];
                    sBB0[i] = bv[i];           sBB1[i] = bv[64 + i];           sBB2[i] = bv[128 + i];
                }
                if (tid < Dn) sBo[tid] = ubout[idx * Dn + tid];
            }
            __syncthreads();

            float h[64];
#pragma unroll
            for (int j = 0; j < 64; j++)
                h[j] = fmaf(fmaxf(fmaf(x, sWi[j], sB0[j]), 0.f), sG0[j], sBB0[j]);
            dense64(h, sW1, sB1, sG1, sBB1);
            dense64(h, sW2, sB2, sG2, sBB2);

            float acc[Dn];
#pragma unroll
            for (int d = 0; d < Dn; d++) acc[d] = sBo[d];
#pragma unroll
            for (int j = 0; j < 64; j++) {
                float hj = h[j];
                const float4 *wr = (const float4 *)(sWo + j * Dn);  // 80B rows: 16B-aligned
                float4 a0 = wr[0], a1 = wr[1], a2 = wr[2], a3 = wr[3], a4 = wr[4];
                acc[0]  = fmaf(hj, a0.x, acc[0]);  acc[1]  = fmaf(hj, a0.y, acc[1]);
                acc[2]  = fmaf(hj, a0.z, acc[2]);  acc[3]  = fmaf(hj, a0.w, acc[3]);
                acc[4]  = fmaf(hj, a1.x, acc[4]);  acc[5]  = fmaf(hj, a1.y, acc[5]);
                acc[6]  = fmaf(hj, a1.z, acc[6]);  acc[7]  = fmaf(hj, a1.w, acc[7]);
                acc[8]  = fmaf(hj, a2.x, acc[8]);  acc[9]  = fmaf(hj, a2.y, acc[9]);
                acc[10] = fmaf(hj, a2.z, acc[10]); acc[11] = fmaf(hj, a2.w, acc[11]);
                acc[12] = fmaf(hj, a3.x, acc[12]); acc[13] = fmaf(hj, a3.y, acc[13]);
                acc[14] = fmaf(hj, a3.z, acc[14]); acc[15] = fmaf(hj, a3.w, acc[15]);
                acc[16] = fmaf(hj, a4.x, acc[16]); acc[17] = fmaf(hj, a4.y, acc[17]);
                acc[18] = fmaf(hj, a4.z, acc[18]); acc[19] = fmaf(hj, a4.w, acc[19]);
            }
#pragma unroll
            for (int d = 0; d < Dn; d++) alpha[d] = acc[d];
        }
    }

    g_xpre[b] = x;
    g_dacc[b] = dacc;
#pragma unroll
    for (int d = 0; d < Dn; d++) g_S[b * Dn + d] = S[d];
}

// ---------------- K2: C0/P0 per asset (blocks 0..19) + alpha_tot (block 20) ----------------
__global__ void __launch_bounds__(256)
k_reduce(const float *__restrict__ x_in, const float *__restrict__ S0,
         const float *__restrict__ optW, const float *__restrict__ optb,
         const float *__restrict__ KW,   const float *__restrict__ Kb)
{
    __shared__ float sA[256], sB[256];
    const int tid = threadIdx.x, blk = blockIdx.x;
    const float disc = expf(-0.02f);       // exp(-R*T)
    const float fq   = expf(-0.04f);       // exp((R-MU)*T): S_Q = S/S0 * fq

    if (blk < Dn) {
        const int d = blk;
        const float wc = KW[d], bc = Kb[d], wp = KW[Dn + d], bp = Kb[Dn + d];
        float cq = 0.f, pq = 0.f;
        for (int b = tid; b < Bsz; b += 256) {
            float xv = x_in[b];
            float SQ = g_S[b * Dn + d] / S0[b * Dn + d] * fq;
            float Kc = fmaf(0.25f, tanhf(fmaf(xv, wc, bc)), 1.0f);
            float Kp = fmaf(0.25f, tanhf(fmaf(xv, wp, bp)), 1.0f);
            cq += fmaxf(SQ - Kc, 0.f);
            pq += fmaxf(Kp - SQ, 0.f);
        }
        sA[tid] = cq; sB[tid] = pq; __syncthreads();
        for (int s = 128; s > 0; s >>= 1) {
            if (tid < s) { sA[tid] += sA[tid + s]; sB[tid] += sB[tid + s]; }
            __syncthreads();
        }
        if (tid == 0) {
            g_stats[d]      = disc * sA[0] / (float)Bsz;
            g_stats[Dn + d] = disc * sB[0] / (float)Bsz;
        }
    } else {
        float asum = 0.f;
        for (int b = tid; b < Bsz; b += 256) {
            float xv = x_in[b];
            float l[41]; float m = -1e30f;
#pragma unroll
            for (int j = 0; j < 41; j++) { l[j] = fmaf(xv, optW[j], optb[j]); m = fmaxf(m, l[j]); }
            float s = 0.f;
#pragma unroll
            for (int j = 0; j < 41; j++) s += __expf(l[j] - m);
            asum += 1.0f - __expf(l[40] - m) / s;   // sum of first 40 softmax entries
        }
        sA[tid] = asum; __syncthreads();
        for (int s = 128; s > 0; s >>= 1) {
            if (tid < s) sA[tid] += sA[tid + s];
            __syncthreads();
        }
        if (tid == 0) {
            g_stats[40] = 1.0f - sA[0] / (float)Bsz;                               // rescale
            g_stats[42] = fmaf(0.25f, tanhf(fmaf(x_in[0], KW[1], Kb[1])), 1.0f);   // loss6 = K[0,1]
        }
    }
}

// ---------------- K3: per-path payoff + final wealth + sortable keys ----------------
__global__ void __launch_bounds__(128)
k_path(const float *__restrict__ x_in, const float *__restrict__ optW,
       const float *__restrict__ optb, const float *__restrict__ KW,
       const float *__restrict__ Kb)
{
    __shared__ float s5[128];
    const int tid = threadIdx.x;
    const int b   = blockIdx.x * 128 + tid;

    float xv = x_in[b];
    float l[41]; float m = -1e30f;
#pragma unroll
    for (int j = 0; j < 41; j++) { l[j] = fmaf(xv, optW[j], optb[j]); m = fmaxf(m, l[j]); }
    float ssum = 0.f;
#pragma unroll
    for (int j = 0; j < 41; j++) { l[j] = __expf(l[j] - m); ssum += l[j]; }
    float inv_s = 1.0f / ssum;

    float rescale = g_stats[40];
    float pay = 0.f, ct0 = 0.f;
#pragma unroll
    for (int d = 0; d < Dn; d++) {
        float Sv = g_S[b * Dn + d];
        float Kc = fmaf(0.25f, tanhf(fmaf(xv, KW[d], Kb[d])), 1.0f);
        float Kp = fmaf(0.25f, tanhf(fmaf(xv, KW[Dn + d], Kb[Dn + d])), 1.0f);
        float CT = fmaxf(Sv - Kc, 0.f) / g_stats[d];
        float PT = fmaxf(Kp - Sv, 0.f) / g_stats[Dn + d];
        pay += (l[d] * inv_s) * CT + (l[Dn + d] * inv_s) * PT;
        if (d == 0) ct0 = CT;
    }
    float xf = rescale * g_xpre[b] - 0.005f * rescale * g_dacc[b] + pay;
    g_xfin[b] = xf;
    unsigned u = __float_as_uint(xf);
    g_keys[b] = (u & 0x80000000u) ? ~u : (u | 0x80000000u);

    s5[tid] = ct0; __syncthreads();
    for (int s = 64; s > 0; s >>= 1) {
        if (tid < s) s5[tid] += s5[tid + s];
        __syncthreads();
    }
    if (tid == 0) g_part5[blockIdx.x] = s5[0];
}

// ---------------- K4: losses (single block) ----------------
__device__ float radix_select_rank(int rank, unsigned *hist /*258*/) {
    unsigned prefix = 0, mask = 0;
    int r = rank;
    for (int shift = 24; shift >= 0; shift -= 8) {
        for (int i = threadIdx.x; i < 256; i += blockDim.x) hist[i] = 0;
        __syncthreads();
        for (int i = threadIdx.x; i < Bsz; i += blockDim.x) {
            unsigned k = g_keys[i];
            if ((k & mask) == prefix) atomicAdd(&hist[(k >> shift) & 255], 1u);
        }
        __syncthreads();
        if (threadIdx.x == 0) {
            unsigned cum = 0; unsigned sel = 0, nr = 0;
            for (int bin = 0; bin < 256; bin++) {
                unsigned c = hist[bin];
                if ((unsigned)r < cum + c) { sel = (unsigned)bin; nr = (unsigned)r - cum; break; }
                cum += c;
            }
            hist[256] = sel; hist[257] = nr;
        }
        __syncthreads();
        prefix |= hist[256] << shift;
        mask   |= 0xFFu << shift;
        r = (int)hist[257];
        __syncthreads();
    }
    return __uint_as_float((prefix & 0x80000000u) ? (prefix ^ 0x80000000u) : ~prefix);
}

__global__ void __launch_bounds__(1024)
k_loss(float *__restrict__ out)
{
    __shared__ double   sd[1024];
    __shared__ int      si[1024];
    __shared__ unsigned hist[258];
    __shared__ float    shf[2];
    const int tid = threadIdx.x;

    // loss5 = mean C_T[:,0]
    double v = (tid < 128) ? (double)g_part5[tid] : 0.0;
    sd[tid] = v; __syncthreads();
    for (int s = 512; s > 0; s >>= 1) { if (tid < s) sd[tid] += sd[tid + s]; __syncthreads(); }
    if (tid == 0) shf[0] = (float)(sd[0] / (double)Bsz);
    __syncthreads();

    // mean
    v = 0.0;
    for (int i = tid; i < Bsz; i += 1024) v += (double)g_xfin[i];
    sd[tid] = v; __syncthreads();
    for (int s = 512; s > 0; s >>= 1) { if (tid < s) sd[tid] += sd[tid + s]; __syncthreads(); }
    double mean = sd[0] / (double)Bsz;
    __syncthreads();

    // variance (two-pass)
    v = 0.0;
    for (int i = tid; i < Bsz; i += 1024) { double dd = (double)g_xfin[i] - mean; v += dd * dd; }
    sd[tid] = v; __syncthreads();
    for (int s = 512; s > 0; s >>= 1) { if (tid < s) sd[tid] += sd[tid + s]; __syncthreads(); }
    double var = sd[0] / (double)Bsz;
    __syncthreads();

    // percentiles: linear interpolation at 0.05*(N-1) and 0.95*(N-1)
    float v819   = radix_select_rank(819, hist);
    float v820   = radix_select_rank(820, hist);
    float v15563 = radix_select_rank(15563, hist);
    float v15564 = radix_select_rank(15564, hist);
    float f5  = 0.05f * 16383.0f - 819.0f;
    float f95 = 0.95f * 16383.0f - 15563.0f;
    float p5  = v819   + f5  * (v820   - v819);
    float p95 = v15563 + f95 * (v15564 - v15563);

    // masked tail sums
    double slo = 0.0, shi = 0.0; int clo = 0, chi = 0;
    for (int i = tid; i < Bsz; i += 1024) {
        float xx = g_xfin[i];
        if (xx < p5)  { slo += (double)xx; clo++; }
        if (xx > p95) { shi += (double)xx; chi++; }
    }
    sd[tid] = slo; si[tid] = clo; __syncthreads();
    for (int s = 512; s > 0; s >>= 1) {
        if (tid < s) { sd[tid] += sd[tid + s]; si[tid] += si[tid + s]; }
        __syncthreads();
    }
    double sumlo = sd[0]; int cntlo = si[0];
    __syncthreads();
    sd[tid] = shi; si[tid] = chi; __syncthreads();
    for (int s = 512; s > 0; s >>= 1) {
        if (tid < s) { sd[tid] += sd[tid + s]; si[tid] += si[tid + s]; }
        __syncthreads();
    }
    double sumhi = sd[0]; int cnthi = si[0];

    if (tid == 0) {
        out[0] = (float)(-mean);
        out[1] = (float)var;
        out[2] = (float)(-sumlo / (double)(cntlo > 1 ? cntlo : 1));
        out[3] = (float)(-sumhi / (double)(cnthi > 1 ? cnthi : 1));
        out[4] = shf[0];
        out[5] = g_stats[42];
        out[6] = g_stats[40];
    }
}

// ---------------- launcher ----------------
extern "C" void kernel_launch(void* const* d_in, const int* in_sizes, int n_in,
                              void* d_out, int out_size)
{
    const float* x_in  = (const float*)d_in[0];
    const float* S0    = (const float*)d_in[1];
    const float* dW    = (const float*)d_in[2];
    const float* u0W   = (const float*)d_in[3];
    const float* u0b   = (const float*)d_in[4];
    const float* uWin  = (const float*)d_in[5];
    const float* uWh   = (const float*)d_in[6];
    const float* ubh   = (const float*)d_in[7];
    const float* bng   = (const float*)d_in[8];
    const float* bnb   = (const float*)d_in[9];
    const float* uWout = (const float*)d_in[10];
    const float* ubout = (const float*)d_in[11];
    const float* optW  = (const float*)d_in[12];
    const float* optb  = (const float*)d_in[13];
    const float* KW    = (const float*)d_in[14];
    const float* Kb    = (const float*)d_in[15];

    k_sim<<<Bsz / 128, 128>>>(x_in, S0, dW, u0W, u0b, uWin, uWh, ubh, bng, bnb, uWout, ubout);
    k_reduce<<<Dn + 1, 256>>>(x_in, S0, optW, optb, KW, Kb);
    k_path<<<Bsz / 128, 128>>>(x_in, optW, optb, KW, Kb);
    k_loss<<<1, 1024>>>((float*)d_out);
}

// round 8
// speedup vs baseline: 1.1952x; 1.1952x over previous
#include <cuda_runtime.h>
#include <math.h>

#define Bsz 16384
#define Dn  20
#define NSTEP 100

// ---------------- device scratch (no allocation allowed) ----------------
__device__ float    g_S[Bsz * Dn];   // final P-measure prices
__device__ float    g_xpre[Bsz];     // wealth after loop (pre-rescale)
__device__ float    g_dacc[Bsz];     // turnover sum
__device__ float    g_xfin[Bsz];     // final wealth
__device__ float    g_stats[48];     // [0..19]=C0, [20..39]=P0, [40]=rescale, [42]=loss6
__device__ float    g_part5[128];    // per-block partials of C_T[:,0]
__device__ double   g_partM[128];    // per-block sum(x)
__device__ double   g_partQ[128];    // per-block sum(x^2)
__device__ unsigned g_keys[Bsz];     // sortable keys of g_xfin

// ---------------- packed fp32x2 helpers ----------------
__device__ __forceinline__ unsigned long long pack2(float lo, float hi) {
    unsigned long long r; asm("mov.b64 %0,{%1,%2};" : "=l"(r) : "f"(lo), "f"(hi)); return r;
}
__device__ __forceinline__ void unpack2(unsigned long long v, float &lo, float &hi) {
    asm("mov.b64 {%0,%1},%2;" : "=f"(lo), "=f"(hi) : "l"(v));
}
__device__ __forceinline__ unsigned long long ffma2(unsigned long long a,
                                                    unsigned long long b,
                                                    unsigned long long c) {
    unsigned long long d;
    asm("fma.rn.f32x2 %0,%1,%2,%3;" : "=l"(d) : "l"(a), "l"(b), "l"(c));
    return d;
}

// Half of a 64x64 dense layer: this thread produces outputs j = s*32..s*32+31
// from the pair-distributed h (32 own values; partner's fetched via shfl).
__device__ __forceinline__ void dense64_half(float *h, int s, int lane,
                                             const float *W, const float *bias,
                                             const float *g, const float *bb) {
    unsigned long long acc[16];
    const ulonglong2 *b4 = (const ulonglong2 *)(bias + s * 32);
#pragma unroll
    for (int p = 0; p < 8; p++) { ulonglong2 t = b4[p]; acc[2*p] = t.x; acc[2*p+1] = t.y; }
    const int src_base = lane & 0xFE;
#pragma unroll
    for (int k = 0; k < 64; k++) {
        float hk = __shfl_sync(0xffffffffu, h[k & 31], src_base | (k >> 5));
        unsigned long long hk2 = pack2(hk, hk);
        const ulonglong2 *w = (const ulonglong2 *)(W + (k << 6) + (s << 5));
#pragma unroll
        for (int p = 0; p < 8; p++) {
            ulonglong2 wv = w[p];
            acc[2*p]   = ffma2(hk2, wv.x, acc[2*p]);
            acc[2*p+1] = ffma2(hk2, wv.y, acc[2*p+1]);
        }
    }
    const float *gs = g + s * 32, *bs = bb + s * 32;
#pragma unroll
    for (int j = 0; j < 16; j++) {
        float lo, hi; unpack2(acc[j], lo, hi);
        h[2*j]   = fmaf(fmaxf(lo, 0.f), gs[2*j],   bs[2*j]);
        h[2*j+1] = fmaf(fmaxf(hi, 0.f), gs[2*j+1], bs[2*j+1]);
    }
}

// ---------------- K1: SDE + policy MLP, TWO threads per path ----------------
__global__ void __launch_bounds__(256)
k_sim(const float *__restrict__ x_in,  const float *__restrict__ S0,
      const float *__restrict__ dW,    const float *__restrict__ u0W,
      const float *__restrict__ u0b,   const float *__restrict__ uWin,
      const float *__restrict__ uWh,   const float *__restrict__ ubh,
      const float *__restrict__ bng,   const float *__restrict__ bnb,
      const float *__restrict__ uWout, const float *__restrict__ ubout)
{
    __shared__ __align__(16) float sm[10132];
    float *sW1 = sm,        *sW2 = sm + 4096, *sWo = sm + 8192;
    float *sWi = sm + 9472, *sB0 = sm + 9536, *sG0 = sm + 9600, *sBB0 = sm + 9664;
    float *sB1 = sm + 9728, *sG1 = sm + 9792, *sBB1 = sm + 9856;
    float *sB2 = sm + 9920, *sG2 = sm + 9984, *sBB2 = sm + 10048, *sBo = sm + 10112;

    const int tid  = threadIdx.x;
    const int lane = tid & 31;
    const int path = blockIdx.x * 128 + (tid >> 1);
    const int s    = tid & 1;            // half index: assets/hidden [s*10..), [s*32..)

    const float sqh = 0.1f;                                   // sqrt(0.01)
    const float SIG = 0.2f;
    const float cS  = (0.06f - 0.5f * 0.2f * 0.2f) * 0.01f;
    const float rh  = 0.02f * 0.01f;
    const float muh = 0.06f * 0.01f;
    const float inv_bn = 1.0f / sqrtf(1.0f + 1e-3f);

    float x = x_in[path];
    float S[10], Nm1[10], alpha[10];
    float dacc = 0.f;
#pragma unroll
    for (int d = 0; d < 10; d++) {
        int gd = s * 10 + d;
        S[d] = S0[path * Dn + gd];
        Nm1[d] = 0.f;
        alpha[d] = fmaf(x, u0W[gd], u0b[gd]);
    }

    // prefetch step 1 dW
    float2 ld[5];
    {
        const float2 *p = (const float2 *)(dW + (size_t)path * Dn + s * 10);
#pragma unroll
        for (int i = 0; i < 5; i++) ld[i] = p[i];
    }

#pragma unroll 1
    for (int n = 1; n <= NSTEP; n++) {
        float dv[10];
#pragma unroll
        for (int i = 0; i < 5; i++) { dv[2*i] = ld[i].x; dv[2*i+1] = ld[i].y; }
        if (n < NSTEP) {
            const float2 *p = (const float2 *)(dW + (size_t)n * Bsz * Dn + (size_t)path * Dn + s * 10);
#pragma unroll
            for (int i = 0; i < 5; i++) ld[i] = p[i];
        }

        float su = 0.f, sus = 0.f;
#pragma unroll
        for (int d = 0; d < 10; d++) {
            float u  = alpha[d];
            float Np = __fdividef(u, S[d]);
            if (n > 1) dacc += fabsf(Np - Nm1[d]);
            Nm1[d] = Np;
            float sdw = SIG * (sqh * dv[d]);
            su  += u;
            sus  = fmaf(u, muh + sdw, sus);
            S[d] *= __expf(cS + sdw);
        }
        // canonical-order pair sums -> both threads compute bit-identical x
        float su_o  = __shfl_xor_sync(0xffffffffu, su, 1);
        float sus_o = __shfl_xor_sync(0xffffffffu, sus, 1);
        float suT  = s ? (su_o + su)   : (su + su_o);
        float susT = s ? (sus_o + sus) : (sus + sus_o);
        x = fmaf(x - suT, rh, x) + susT;

        if ((n % 10) == 0 && n < NSTEP) {         // n = 10..90, uniform across block
            const int idx = n / 10 - 1;
            __syncthreads();
            {
                const float *ws = uWh + (size_t)idx * 2 * 64 * 64;
                for (int i = tid; i < 4096; i += 256) { sW1[i] = ws[i]; sW2[i] = ws[4096 + i]; }
                const float *wo = uWout + (size_t)idx * 64 * Dn;
                for (int i = tid; i < 64 * Dn; i += 256) sWo[i] = wo[i];
                const float *wi = uWin + idx * 64;
                const float *bh = ubh + idx * 192;
                const float *gg = bng + idx * 192;
                const float *bv = bnb + idx * 192;
                for (int i = tid; i < 64; i += 256) {
                    sWi[i] = wi[i];
                    sB0[i] = bh[i];            sB1[i] = bh[64 + i];            sB2[i] = bh[128 + i];
                    sG0[i] = inv_bn * gg[i];   sG1[i] = inv_bn * gg[64 + i];   sG2[i] = inv_bn * gg[128 + i];
                    sBB0[i] = bv[i];           sBB1[i] = bv[64 + i];           sBB2[i] = bv[128 + i];
                }
                if (tid < Dn) sBo[tid] = ubout[idx * Dn + tid];
            }
            __syncthreads();

            float h[32];
#pragma unroll
            for (int jj = 0; jj < 32; jj++) {
                int j = s * 32 + jj;
                h[jj] = fmaf(fmaxf(fmaf(x, sWi[j], sB0[j]), 0.f), sG0[j], sBB0[j]);
            }
            dense64_half(h, s, lane, sW1, sB1, sG1, sBB1);
            dense64_half(h, s, lane, sW2, sB2, sG2, sBB2);

            float acc[10];
            const float *bo = sBo + s * 10;
#pragma unroll
            for (int d = 0; d < 10; d++) acc[d] = bo[d];
            const int src_base = lane & 0xFE;
#pragma unroll
            for (int k = 0; k < 64; k++) {
                float hj = __shfl_sync(0xffffffffu, h[k & 31], src_base | (k >> 5));
                const float2 *wr = (const float2 *)(sWo + k * Dn + s * 10);
                float2 a0 = wr[0], a1 = wr[1], a2 = wr[2], a3 = wr[3], a4 = wr[4];
                acc[0] = fmaf(hj, a0.x, acc[0]); acc[1] = fmaf(hj, a0.y, acc[1]);
                acc[2] = fmaf(hj, a1.x, acc[2]); acc[3] = fmaf(hj, a1.y, acc[3]);
                acc[4] = fmaf(hj, a2.x, acc[4]); acc[5] = fmaf(hj, a2.y, acc[5]);
                acc[6] = fmaf(hj, a3.x, acc[6]); acc[7] = fmaf(hj, a3.y, acc[7]);
                acc[8] = fmaf(hj, a4.x, acc[8]); acc[9] = fmaf(hj, a4.y, acc[9]);
            }
#pragma unroll
            for (int d = 0; d < 10; d++) alpha[d] = acc[d];
        }
    }

    float dacc_o = __shfl_xor_sync(0xffffffffu, dacc, 1);
    if (s == 0) {
        g_xpre[path] = x;
        g_dacc[path] = dacc + dacc_o;   // half0 + half1
    }
#pragma unroll
    for (int d = 0; d < 10; d++) g_S[path * Dn + s * 10 + d] = S[d];
}

// ---------------- K2: C0/P0 per asset (blocks 0..19) + alpha_tot (block 20) ----------------
__global__ void __launch_bounds__(256)
k_reduce(const float *__restrict__ x_in, const float *__restrict__ S0,
         const float *__restrict__ optW, const float *__restrict__ optb,
         const float *__restrict__ KW,   const float *__restrict__ Kb)
{
    __shared__ float sA[256], sB[256];
    const int tid = threadIdx.x, blk = blockIdx.x;
    const float disc = expf(-0.02f);       // exp(-R*T)
    const float fq   = expf(-0.04f);       // exp((R-MU)*T): S_Q = S/S0 * fq

    if (blk < Dn) {
        const int d = blk;
        const float wc = KW[d], bc = Kb[d], wp = KW[Dn + d], bp = Kb[Dn + d];
        float cq = 0.f, pq = 0.f;
        for (int b = tid; b < Bsz; b += 256) {
            float xv = x_in[b];
            float SQ = g_S[b * Dn + d] / S0[b * Dn + d] * fq;
            float Kc = fmaf(0.25f, tanhf(fmaf(xv, wc, bc)), 1.0f);
            float Kp = fmaf(0.25f, tanhf(fmaf(xv, wp, bp)), 1.0f);
            cq += fmaxf(SQ - Kc, 0.f);
            pq += fmaxf(Kp - SQ, 0.f);
        }
        sA[tid] = cq; sB[tid] = pq; __syncthreads();
        for (int s = 128; s > 0; s >>= 1) {
            if (tid < s) { sA[tid] += sA[tid + s]; sB[tid] += sB[tid + s]; }
            __syncthreads();
        }
        if (tid == 0) {
            g_stats[d]      = disc * sA[0] / (float)Bsz;
            g_stats[Dn + d] = disc * sB[0] / (float)Bsz;
        }
    } else {
        float asum = 0.f;
        for (int b = tid; b < Bsz; b += 256) {
            float xv = x_in[b];
            float l[41]; float m = -1e30f;
#pragma unroll
            for (int j = 0; j < 41; j++) { l[j] = fmaf(xv, optW[j], optb[j]); m = fmaxf(m, l[j]); }
            float s = 0.f;
#pragma unroll
            for (int j = 0; j < 41; j++) s += __expf(l[j] - m);
            asum += 1.0f - __expf(l[40] - m) / s;   // sum of first 40 softmax entries
        }
        sA[tid] = asum; __syncthreads();
        for (int s = 128; s > 0; s >>= 1) {
            if (tid < s) sA[tid] += sA[tid + s];
            __syncthreads();
        }
        if (tid == 0) {
            g_stats[40] = 1.0f - sA[0] / (float)Bsz;                               // rescale
            g_stats[42] = fmaf(0.25f, tanhf(fmaf(x_in[0], KW[1], Kb[1])), 1.0f);   // loss6 = K[0,1]
        }
    }
}

// ---------------- K3: per-path payoff + final wealth + keys + mean/sumsq partials ----------------
__global__ void __launch_bounds__(128)
k_path(const float *__restrict__ x_in, const float *__restrict__ optW,
       const float *__restrict__ optb, const float *__restrict__ KW,
       const float *__restrict__ Kb)
{
    __shared__ float  s5[128];
    __shared__ double sdm[128], sdq[128];
    const int tid = threadIdx.x;
    const int b   = blockIdx.x * 128 + tid;

    float xv = x_in[b];
    float l[41]; float m = -1e30f;
#pragma unroll
    for (int j = 0; j < 41; j++) { l[j] = fmaf(xv, optW[j], optb[j]); m = fmaxf(m, l[j]); }
    float ssum = 0.f;
#pragma unroll
    for (int j = 0; j < 41; j++) { l[j] = __expf(l[j] - m); ssum += l[j]; }
    float inv_s = 1.0f / ssum;

    float rescale = g_stats[40];
    float pay = 0.f, ct0 = 0.f;
#pragma unroll
    for (int d = 0; d < Dn; d++) {
        float Sv = g_S[b * Dn + d];
        float Kc = fmaf(0.25f, tanhf(fmaf(xv, KW[d], Kb[d])), 1.0f);
        float Kp = fmaf(0.25f, tanhf(fmaf(xv, KW[Dn + d], Kb[Dn + d])), 1.0f);
        float CT = fmaxf(Sv - Kc, 0.f) / g_stats[d];
        float PT = fmaxf(Kp - Sv, 0.f) / g_stats[Dn + d];
        pay += (l[d] * inv_s) * CT + (l[Dn + d] * inv_s) * PT;
        if (d == 0) ct0 = CT;
    }
    float xf = rescale * g_xpre[b] - 0.005f * rescale * g_dacc[b] + pay;
    g_xfin[b] = xf;
    unsigned u = __float_as_uint(xf);
    g_keys[b] = (u & 0x80000000u) ? ~u : (u | 0x80000000u);

    s5[tid]  = ct0;
    sdm[tid] = (double)xf;
    sdq[tid] = (double)xf * (double)xf;
    __syncthreads();
    for (int s = 64; s > 0; s >>= 1) {
        if (tid < s) { s5[tid] += s5[tid + s]; sdm[tid] += sdm[tid + s]; sdq[tid] += sdq[tid + s]; }
        __syncthreads();
    }
    if (tid == 0) {
        g_part5[blockIdx.x] = s5[0];
        g_partM[blockIdx.x] = sdm[0];
        g_partQ[blockIdx.x] = sdq[0];
    }
}

// ---------------- K4: losses (single block, 1024 threads) ----------------
__device__ __forceinline__ float key_to_float(unsigned k) {
    unsigned u = (k & 0x80000000u) ? (k ^ 0x80000000u) : ~k;
    return __uint_as_float(u);
}

// radix-select the rank-th smallest key. Warp-aggregated histogram, warp scan.
__device__ unsigned radix_select(int rank, unsigned *hist, unsigned *selres) {
    unsigned prefix = 0, mask = 0;
    int r = rank;
    const int tid = threadIdx.x;
    const int lane = tid & 31;
    for (int shift = 24; shift >= 0; shift -= 8) {
        if (tid < 256) hist[tid] = 0;
        __syncthreads();
        for (int i = tid; i < Bsz; i += 1024) {      // 16384 % 1024 == 0: full warps
            unsigned k = g_keys[i];
            unsigned bin = ((k & mask) == prefix) ? ((k >> shift) & 255u) : 256u;
            unsigned peers = __match_any_sync(0xffffffffu, bin);
            if (bin < 256u && lane == (__ffs(peers) - 1))
                atomicAdd(&hist[bin], (unsigned)__popc(peers));
        }
        __syncthreads();
        if (tid < 32) {
            unsigned carry = 0;
#pragma unroll
            for (int c = 0; c < 8; c++) {
                unsigned v = hist[c * 32 + lane];
                unsigned orig = v;
#pragma unroll
                for (int o = 1; o < 32; o <<= 1) {
                    unsigned t = __shfl_up_sync(0xffffffffu, v, o);
                    if (lane >= o) v += t;
                }
                unsigned inc = v + carry;
                unsigned exc = inc - orig;
                if ((unsigned)r >= exc && (unsigned)r < inc) {
                    selres[0] = (unsigned)(c * 32 + lane);
                    selres[1] = (unsigned)r - exc;
                }
                carry += __shfl_sync(0xffffffffu, v, 31);
            }
        }
        __syncthreads();
        prefix |= selres[0] << shift;
        mask   |= 0xFFu << shift;
        r = (int)selres[1];
        __syncthreads();
    }
    return prefix;
}

__global__ void __launch_bounds__(1024)
k_loss(float *__restrict__ out)
{
    __shared__ double   sd[1024];
    __shared__ int      si[1024];
    __shared__ unsigned su[1024];
    __shared__ unsigned hist[256];
    __shared__ unsigned selres[2];
    const int tid = threadIdx.x;

    // loss5 / mean / sumsq from per-block partials (128 each)
    double vm = 0.0, vq = 0.0, v5 = 0.0;
    if (tid < 128) { vm = g_partM[tid]; vq = g_partQ[tid]; v5 = (double)g_part5[tid]; }
    sd[tid] = vm; __syncthreads();
    for (int s = 512; s > 0; s >>= 1) { if (tid < s) sd[tid] += sd[tid + s]; __syncthreads(); }
    double mean = sd[0] / (double)Bsz;
    __syncthreads();
    sd[tid] = vq; __syncthreads();
    for (int s = 512; s > 0; s >>= 1) { if (tid < s) sd[tid] += sd[tid + s]; __syncthreads(); }
    double var = sd[0] / (double)Bsz - mean * mean;
    __syncthreads();
    sd[tid] = v5; __syncthreads();
    for (int s = 512; s > 0; s >>= 1) { if (tid < s) sd[tid] += sd[tid + s]; __syncthreads(); }
    float loss5 = (float)(sd[0] / (double)Bsz);
    __syncthreads();

    // order statistics 819 and 15563; 820 / 15564 derived below
    unsigned k5  = radix_select(819,   hist, selres);
    unsigned k95 = radix_select(15563, hist, selres);

    // one pass: count(keys <= k) and min(keys > k) for both thresholds
    int c5 = 0, c95 = 0;
    unsigned mg5 = 0xffffffffu, mg95 = 0xffffffffu;
    for (int i = tid; i < Bsz; i += 1024) {
        unsigned k = g_keys[i];
        if (k <= k5)  c5++;  else mg5  = min(mg5,  k);
        if (k <= k95) c95++; else mg95 = min(mg95, k);
    }
    si[tid] = c5; su[tid] = mg5; __syncthreads();
    for (int s = 512; s > 0; s >>= 1) {
        if (tid < s) { si[tid] += si[tid + s]; su[tid] = min(su[tid], su[tid + s]); }
        __syncthreads();
    }
    int cle5 = si[0]; unsigned mgt5 = su[0];
    __syncthreads();
    si[tid] = c95; su[tid] = mg95; __syncthreads();
    for (int s = 512; s > 0; s >>= 1) {
        if (tid < s) { si[tid] += si[tid + s]; su[tid] = min(su[tid], su[tid + s]); }
        __syncthreads();
    }
    int cle95 = si[0]; unsigned mgt95 = su[0];
    __syncthreads();

    float v819   = key_to_float(k5);
    float v820   = (820 < cle5) ? v819 : key_to_float(mgt5);
    float v15563 = key_to_float(k95);
    float v15564 = (15564 < cle95) ? v15563 : key_to_float(mgt95);
    const float f5  = 0.05f * 16383.0f - 819.0f;     // 0.15
    const float f95 = 0.95f * 16383.0f - 15563.0f;   // 0.85
    float p5  = v819   + f5  * (v820   - v819);
    float p95 = v15563 + f95 * (v15564 - v15563);

    // masked tail sums (one pass)
    double slo = 0.0, shi = 0.0; int clo = 0, chi = 0;
    for (int i = tid; i < Bsz; i += 1024) {
        float xx = g_xfin[i];
        if (xx < p5)  { slo += (double)xx; clo++; }
        if (xx > p95) { shi += (double)xx; chi++; }
    }
    sd[tid] = slo; si[tid] = clo; __syncthreads();
    for (int s = 512; s > 0; s >>= 1) {
        if (tid < s) { sd[tid] += sd[tid + s]; si[tid] += si[tid + s]; }
        __syncthreads();
    }
    double sumlo = sd[0]; int cntlo = si[0];
    __syncthreads();
    sd[tid] = shi; si[tid] = chi; __syncthreads();
    for (int s = 512; s > 0; s >>= 1) {
        if (tid < s) { sd[tid] += sd[tid + s]; si[tid] += si[tid + s]; }
        __syncthreads();
    }
    double sumhi = sd[0]; int cnthi = si[0];

    if (tid == 0) {
        out[0] = (float)(-mean);
        out[1] = (float)var;
        out[2] = (float)(-sumlo / (double)(cntlo > 1 ? cntlo : 1));
        out[3] = (float)(-sumhi / (double)(cnthi > 1 ? cnthi : 1));
        out[4] = loss5;
        out[5] = g_stats[42];
        out[6] = g_stats[40];
    }
}

// ---------------- launcher ----------------
extern "C" void kernel_launch(void* const* d_in, const int* in_sizes, int n_in,
                              void* d_out, int out_size)
{
    const float* x_in  = (const float*)d_in[0];
    const float* S0    = (const float*)d_in[1];
    const float* dW    = (const float*)d_in[2];
    const float* u0W   = (const float*)d_in[3];
    const float* u0b   = (const float*)d_in[4];
    const float* uWin  = (const float*)d_in[5];
    const float* uWh   = (const float*)d_in[6];
    const float* ubh   = (const float*)d_in[7];
    const float* bng   = (const float*)d_in[8];
    const float* bnb   = (const float*)d_in[9];
    const float* uWout = (const float*)d_in[10];
    const float* ubout = (const float*)d_in[11];
    const float* optW  = (const float*)d_in[12];
    const float* optb  = (const float*)d_in[13];
    const float* KW    = (const float*)d_in[14];
    const float* Kb    = (const float*)d_in[15];

    k_sim<<<Bsz / 128, 256>>>(x_in, S0, dW, u0W, u0b, uWin, uWh, ubh, bng, bnb, uWout, ubout);
    k_reduce<<<Dn + 1, 256>>>(x_in, S0, optW, optb, KW, Kb);
    k_path<<<Bsz / 128, 128>>>(x_in, optW, optb, KW, Kb);
    k_loss<<<1, 1024>>>((float*)d_out);
}

// round 9
// speedup vs baseline: 1.3358x; 1.1176x over previous
#include <cuda_runtime.h>
#include <math.h>

#define Bsz 16384
#define Dn  20
#define NSTEP 100

// ---------------- device scratch (no allocation allowed) ----------------
__device__ float    g_ST [2 * Dn * Bsz]; // [0..19]: S transposed [d][b]; [20..39] unused pad
__device__ float    g_SQT[Dn * Bsz];     // S_Q transposed [d][b]
__device__ float    g_KT [2 * Dn * Bsz]; // strikes transposed: [d][b] calls, [20+d][b] puts
__device__ float    g_wT [2 * Dn * Bsz]; // softmax option weights transposed
__device__ float    g_xpre[Bsz];
__device__ float    g_dacc[Bsz];
__device__ float    g_xfin[Bsz];
__device__ float    g_stats[48];         // [0..19]=1/C0, [20..39]=1/P0, [40]=rescale, [42]=loss6
__device__ float    g_pA[128];           // alpha_tot partials
__device__ float    g_pC[Dn * 8];        // C0 partials [d][part]
__device__ float    g_pP[Dn * 8];        // P0 partials
__device__ float    g_part5[128];        // per-block partials of C_T[:,0]
__device__ double   g_partM[128];        // per-block sum(x)
__device__ double   g_partQ[128];        // per-block sum(x^2)
__device__ unsigned g_keys[Bsz];

// ---------------- packed fp32x2 helpers ----------------
__device__ __forceinline__ unsigned long long pack2(float lo, float hi) {
    unsigned long long r; asm("mov.b64 %0,{%1,%2};" : "=l"(r) : "f"(lo), "f"(hi)); return r;
}
__device__ __forceinline__ void unpack2(unsigned long long v, float &lo, float &hi) {
    asm("mov.b64 {%0,%1},%2;" : "=f"(lo), "=f"(hi) : "l"(v));
}
__device__ __forceinline__ unsigned long long ffma2(unsigned long long a,
                                                    unsigned long long b,
                                                    unsigned long long c) {
    unsigned long long d;
    asm("fma.rn.f32x2 %0,%1,%2,%3;" : "=l"(d) : "l"(a), "l"(b), "l"(c));
    return d;
}

// Half of a 64x64 dense layer (pair-split): outputs j = s*32..s*32+31.
__device__ __forceinline__ void dense64_half(float *h, int s, int lane,
                                             const float *W, const float *bias,
                                             const float *g, const float *bb) {
    unsigned long long acc[16];
    const ulonglong2 *b4 = (const ulonglong2 *)(bias + s * 32);
#pragma unroll
    for (int p = 0; p < 8; p++) { ulonglong2 t = b4[p]; acc[2*p] = t.x; acc[2*p+1] = t.y; }
    const int src_base = lane & 0xFE;
#pragma unroll
    for (int k = 0; k < 64; k++) {
        float hk = __shfl_sync(0xffffffffu, h[k & 31], src_base | (k >> 5));
        unsigned long long hk2 = pack2(hk, hk);
        const ulonglong2 *w = (const ulonglong2 *)(W + (k << 6) + (s << 5));
#pragma unroll
        for (int p = 0; p < 8; p++) {
            ulonglong2 wv = w[p];
            acc[2*p]   = ffma2(hk2, wv.x, acc[2*p]);
            acc[2*p+1] = ffma2(hk2, wv.y, acc[2*p+1]);
        }
    }
    const float *gs = g + s * 32, *bs = bb + s * 32;
#pragma unroll
    for (int j = 0; j < 16; j++) {
        float lo, hi; unpack2(acc[j], lo, hi);
        h[2*j]   = fmaf(fmaxf(lo, 0.f), gs[2*j],   bs[2*j]);
        h[2*j+1] = fmaf(fmaxf(hi, 0.f), gs[2*j+1], bs[2*j+1]);
    }
}

// ---------------- K0: strikes + softmax weights + alpha_tot partials ----------------
__global__ void __launch_bounds__(128)
k_prep(const float *__restrict__ x_in, const float *__restrict__ optW,
       const float *__restrict__ optb, const float *__restrict__ KW,
       const float *__restrict__ Kb)
{
    __shared__ float sA[128];
    const int tid = threadIdx.x;
    const int b   = blockIdx.x * 128 + tid;
    float xv = x_in[b];

    float l[41]; float m = -1e30f;
#pragma unroll
    for (int j = 0; j < 41; j++) { l[j] = fmaf(xv, optW[j], optb[j]); m = fmaxf(m, l[j]); }
    float ssum = 0.f;
#pragma unroll
    for (int j = 0; j < 41; j++) { l[j] = __expf(l[j] - m); ssum += l[j]; }
    float inv_s = 1.0f / ssum;
#pragma unroll
    for (int j = 0; j < 40; j++) g_wT[j * Bsz + b] = l[j] * inv_s;

#pragma unroll
    for (int j = 0; j < 40; j++)
        g_KT[j * Bsz + b] = fmaf(0.25f, tanhf(fmaf(xv, KW[j], Kb[j])), 1.0f);

    sA[tid] = 1.0f - l[40] * inv_s;   // sum of first 40 softmax entries
    __syncthreads();
    for (int s = 64; s > 0; s >>= 1) {
        if (tid < s) sA[tid] += sA[tid + s];
        __syncthreads();
    }
    if (tid == 0) g_pA[blockIdx.x] = sA[0];
}

// ---------------- K1: SDE + policy MLP, TWO threads per path ----------------
__global__ void __launch_bounds__(128)
k_sim(const float *__restrict__ x_in,  const float *__restrict__ S0,
      const float *__restrict__ dW,    const float *__restrict__ u0W,
      const float *__restrict__ u0b,   const float *__restrict__ uWin,
      const float *__restrict__ uWh,   const float *__restrict__ ubh,
      const float *__restrict__ bng,   const float *__restrict__ bnb,
      const float *__restrict__ uWout, const float *__restrict__ ubout)
{
    __shared__ __align__(16) float sm[10132];
    float *sW1 = sm,        *sW2 = sm + 4096, *sWo = sm + 8192;
    float *sWi = sm + 9472, *sB0 = sm + 9536, *sG0 = sm + 9600, *sBB0 = sm + 9664;
    float *sB1 = sm + 9728, *sG1 = sm + 9792, *sBB1 = sm + 9856;
    float *sB2 = sm + 9920, *sG2 = sm + 9984, *sBB2 = sm + 10048, *sBo = sm + 10112;

    const int tid  = threadIdx.x;
    const int lane = tid & 31;
    const int path = blockIdx.x * 64 + (tid >> 1);
    const int s    = tid & 1;

    const float sqh = 0.1f;
    const float SIG = 0.2f;
    const float cS  = (0.06f - 0.5f * 0.2f * 0.2f) * 0.01f;
    const float rh  = 0.02f * 0.01f;
    const float muh = 0.06f * 0.01f;
    const float inv_bn = 1.0f / sqrtf(1.0f + 1e-3f);
    const float fq  = expf(-0.04f);       // exp((R-MU)*T)

    float x = x_in[path];
    float S[10], Nm1[10], alpha[10];
    float dacc = 0.f;
#pragma unroll
    for (int d = 0; d < 10; d++) {
        int gd = s * 10 + d;
        S[d] = S0[path * Dn + gd];
        Nm1[d] = 0.f;
        alpha[d] = fmaf(x, u0W[gd], u0b[gd]);
    }

    float2 ld[5];
    {
        const float2 *p = (const float2 *)(dW + (size_t)path * Dn + s * 10);
#pragma unroll
        for (int i = 0; i < 5; i++) ld[i] = p[i];
    }

#pragma unroll 1
    for (int n = 1; n <= NSTEP; n++) {
        float dv[10];
#pragma unroll
        for (int i = 0; i < 5; i++) { dv[2*i] = ld[i].x; dv[2*i+1] = ld[i].y; }
        if (n < NSTEP) {
            const float2 *p = (const float2 *)(dW + (size_t)n * Bsz * Dn + (size_t)path * Dn + s * 10);
#pragma unroll
            for (int i = 0; i < 5; i++) ld[i] = p[i];
        }

        float su = 0.f, sus = 0.f;
#pragma unroll
        for (int d = 0; d < 10; d++) {
            float u  = alpha[d];
            float Np = __fdividef(u, S[d]);
            if (n > 1) dacc += fabsf(Np - Nm1[d]);
            Nm1[d] = Np;
            float sdw = SIG * (sqh * dv[d]);
            su  += u;
            sus  = fmaf(u, muh + sdw, sus);
            S[d] *= __expf(cS + sdw);
        }
        float su_o  = __shfl_xor_sync(0xffffffffu, su, 1);
        float sus_o = __shfl_xor_sync(0xffffffffu, sus, 1);
        float suT  = s ? (su_o + su)   : (su + su_o);
        float susT = s ? (sus_o + sus) : (sus + sus_o);
        x = fmaf(x - suT, rh, x) + susT;

        if ((n % 10) == 0 && n < NSTEP) {
            const int idx = n / 10 - 1;
            __syncthreads();
            {
                const float *ws = uWh + (size_t)idx * 2 * 64 * 64;
                for (int i = tid; i < 4096; i += 128) { sW1[i] = ws[i]; sW2[i] = ws[4096 + i]; }
                const float *wo = uWout + (size_t)idx * 64 * Dn;
                for (int i = tid; i < 64 * Dn; i += 128) sWo[i] = wo[i];
                const float *wi = uWin + idx * 64;
                const float *bh = ubh + idx * 192;
                const float *gg = bng + idx * 192;
                const float *bv = bnb + idx * 192;
                for (int i = tid; i < 64; i += 128) {
                    sWi[i] = wi[i];
                    sB0[i] = bh[i];            sB1[i] = bh[64 + i];            sB2[i] = bh[128 + i];
                    sG0[i] = inv_bn * gg[i];   sG1[i] = inv_bn * gg[64 + i];   sG2[i] = inv_bn * gg[128 + i];
                    sBB0[i] = bv[i];           sBB1[i] = bv[64 + i];           sBB2[i] = bv[128 + i];
                }
                if (tid < Dn) sBo[tid] = ubout[idx * Dn + tid];
            }
            __syncthreads();

            float h[32];
#pragma unroll
            for (int jj = 0; jj < 32; jj++) {
                int j = s * 32 + jj;
                h[jj] = fmaf(fmaxf(fmaf(x, sWi[j], sB0[j]), 0.f), sG0[j], sBB0[j]);
            }
            dense64_half(h, s, lane, sW1, sB1, sG1, sBB1);
            dense64_half(h, s, lane, sW2, sB2, sG2, sBB2);

            float acc[10];
            const float *bo = sBo + s * 10;
#pragma unroll
            for (int d = 0; d < 10; d++) acc[d] = bo[d];
            const int src_base = lane & 0xFE;
#pragma unroll
            for (int k = 0; k < 64; k++) {
                float hj = __shfl_sync(0xffffffffu, h[k & 31], src_base | (k >> 5));
                const float2 *wr = (const float2 *)(sWo + k * Dn + s * 10);
                float2 a0 = wr[0], a1 = wr[1], a2 = wr[2], a3 = wr[3], a4 = wr[4];
                acc[0] = fmaf(hj, a0.x, acc[0]); acc[1] = fmaf(hj, a0.y, acc[1]);
                acc[2] = fmaf(hj, a1.x, acc[2]); acc[3] = fmaf(hj, a1.y, acc[3]);
                acc[4] = fmaf(hj, a2.x, acc[4]); acc[5] = fmaf(hj, a2.y, acc[5]);
                acc[6] = fmaf(hj, a3.x, acc[6]); acc[7] = fmaf(hj, a3.y, acc[7]);
                acc[8] = fmaf(hj, a4.x, acc[8]); acc[9] = fmaf(hj, a4.y, acc[9]);
            }
#pragma unroll
            for (int d = 0; d < 10; d++) alpha[d] = acc[d];
        }
    }

    float dacc_o = __shfl_xor_sync(0xffffffffu, dacc, 1);
    if (s == 0) {
        g_xpre[path] = x;
        g_dacc[path] = dacc + dacc_o;
    }
#pragma unroll
    for (int d = 0; d < 10; d++) {
        int gd = s * 10 + d;
        g_ST[gd * Bsz + path]  = S[d];
        g_SQT[gd * Bsz + path] = S[d] / S0[path * Dn + gd] * fq;
    }
}

// ---------------- K2: C0/P0 partials (grid 160 = 20 assets x 8 parts) ----------------
__global__ void __launch_bounds__(256)
k_reduce()
{
    __shared__ float sA[256], sB[256];
    const int tid  = threadIdx.x;
    const int d    = blockIdx.x >> 3;
    const int part = blockIdx.x & 7;
    const float *SQ = g_SQT + d * Bsz;
    const float *Kc = g_KT  + d * Bsz;
    const float *Kp = g_KT  + (Dn + d) * Bsz;

    float cq = 0.f, pq = 0.f;
    const int base = part * 2048;
#pragma unroll
    for (int k = 0; k < 8; k++) {
        int b = base + k * 256 + tid;
        float sq = SQ[b];
        cq += fmaxf(sq - Kc[b], 0.f);
        pq += fmaxf(Kp[b] - sq, 0.f);
    }
    sA[tid] = cq; sB[tid] = pq; __syncthreads();
    for (int s = 128; s > 0; s >>= 1) {
        if (tid < s) { sA[tid] += sA[tid + s]; sB[tid] += sB[tid + s]; }
        __syncthreads();
    }
    if (tid == 0) { g_pC[d * 8 + part] = sA[0]; g_pP[d * 8 + part] = sB[0]; }
}

// ---------------- K3: finalize stats ----------------
__global__ void __launch_bounds__(256)
k_fin()
{
    __shared__ float sA[256];
    const int tid = threadIdx.x;
    const float disc = expf(-0.02f);
    if (tid < 20) {
        float s = 0.f;
#pragma unroll
        for (int p = 0; p < 8; p++) s += g_pC[tid * 8 + p];
        g_stats[tid] = (float)Bsz / (disc * s);          // 1/C0
    } else if (tid < 40) {
        int d = tid - 20;
        float s = 0.f;
#pragma unroll
        for (int p = 0; p < 8; p++) s += g_pP[d * 8 + p];
        g_stats[tid] = (float)Bsz / (disc * s);          // 1/P0
    }
    sA[tid] = (tid < 128) ? g_pA[tid] : 0.f;
    __syncthreads();
    for (int s = 128; s > 0; s >>= 1) {
        if (tid < s) sA[tid] += sA[tid + s];
        __syncthreads();
    }
    if (tid == 0) {
        g_stats[40] = 1.0f - sA[0] / (float)Bsz;   // rescale
        g_stats[42] = g_KT[Bsz + 0];               // loss6 = K[0,1]
    }
}

// ---------------- K4: per-path payoff + keys + moment partials ----------------
__global__ void __launch_bounds__(128)
k_path()
{
    __shared__ float  s5[128];
    __shared__ double sdm[128], sdq[128];
    const int tid = threadIdx.x;
    const int b   = blockIdx.x * 128 + tid;

    float rescale = g_stats[40];
    float pay = 0.f, ct0 = 0.f;
#pragma unroll
    for (int d = 0; d < Dn; d++) {
        float Sv = g_ST[d * Bsz + b];
        float CT = fmaxf(Sv - g_KT[d * Bsz + b], 0.f) * g_stats[d];
        float PT = fmaxf(g_KT[(Dn + d) * Bsz + b] - Sv, 0.f) * g_stats[Dn + d];
        pay += g_wT[d * Bsz + b] * CT + g_wT[(Dn + d) * Bsz + b] * PT;
        if (d == 0) ct0 = CT;
    }
    float xf = rescale * g_xpre[b] - 0.005f * rescale * g_dacc[b] + pay;
    g_xfin[b] = xf;
    unsigned u = __float_as_uint(xf);
    g_keys[b] = (u & 0x80000000u) ? ~u : (u | 0x80000000u);

    s5[tid]  = ct0;
    sdm[tid] = (double)xf;
    sdq[tid] = (double)xf * (double)xf;
    __syncthreads();
    for (int s = 64; s > 0; s >>= 1) {
        if (tid < s) { s5[tid] += s5[tid + s]; sdm[tid] += sdm[tid + s]; sdq[tid] += sdq[tid + s]; }
        __syncthreads();
    }
    if (tid == 0) {
        g_part5[blockIdx.x] = s5[0];
        g_partM[blockIdx.x] = sdm[0];
        g_partQ[blockIdx.x] = sdq[0];
    }
}

// ---------------- K5: losses (single block, 1024 threads) ----------------
__device__ __forceinline__ float key_to_float(unsigned k) {
    unsigned u = (k & 0x80000000u) ? (k ^ 0x80000000u) : ~k;
    return __uint_as_float(u);
}

// radix-select rank-th smallest. Warp-private histograms: ZERO atomics.
__device__ unsigned radix_select(int rank, unsigned *ubuf /*32x256*/,
                                 unsigned *tot /*256*/, unsigned *selres /*2*/)
{
    unsigned prefix = 0, mask = 0;
    int r = rank;
    const int tid = threadIdx.x;
    const int lane = tid & 31;
    const int w = tid >> 5;
    unsigned *mine = ubuf + w * 256;
    for (int shift = 24; shift >= 0; shift -= 8) {
#pragma unroll
        for (int i = 0; i < 8; i++) ubuf[i * 1024 + tid] = 0;
        __syncthreads();
        for (int i = tid; i < Bsz; i += 1024) {
            unsigned k = g_keys[i];
            unsigned bin = ((k & mask) == prefix) ? ((k >> shift) & 255u) : 256u;
            unsigned peers = __match_any_sync(0xffffffffu, bin);
            if (bin < 256u && lane == (__ffs(peers) - 1))
                mine[bin] += (unsigned)__popc(peers);   // warp-private: race-free
        }
        __syncthreads();
        if (tid < 256) {
            unsigned s = 0;
#pragma unroll
            for (int ww = 0; ww < 32; ww++) s += ubuf[ww * 256 + tid];
            tot[tid] = s;
        }
        __syncthreads();
        if (tid < 32) {
            unsigned carry = 0;
#pragma unroll
            for (int c = 0; c < 8; c++) {
                unsigned v = tot[c * 32 + lane], orig = v;
#pragma unroll
                for (int o = 1; o < 32; o <<= 1) {
                    unsigned t = __shfl_up_sync(0xffffffffu, v, o);
                    if (lane >= o) v += t;
                }
                unsigned inc = v + carry, exc = inc - orig;
                if ((unsigned)r >= exc && (unsigned)r < inc) {
                    selres[0] = (unsigned)(c * 32 + lane);
                    selres[1] = (unsigned)r - exc;
                }
                carry += __shfl_sync(0xffffffffu, v, 31);
            }
        }
        __syncthreads();
        prefix |= selres[0] << shift;
        mask   |= 0xFFu << shift;
        r = (int)selres[1];
        __syncthreads();
    }
    return prefix;
}

__global__ void __launch_bounds__(1024)
k_loss(float *__restrict__ out)
{
    __shared__ double   sd[1024];      // 8 KB (aliased as tot[] during radix)
    __shared__ unsigned ubuf[8192];    // 32 KB: warp hists / si / su
    __shared__ unsigned selres[2];
    const int tid = threadIdx.x;

    // moments + loss5 from per-block partials
    double vm = 0.0, vq = 0.0, v5 = 0.0;
    if (tid < 128) { vm = g_partM[tid]; vq = g_partQ[tid]; v5 = (double)g_part5[tid]; }
    sd[tid] = vm; __syncthreads();
    for (int s = 512; s > 0; s >>= 1) { if (tid < s) sd[tid] += sd[tid + s]; __syncthreads(); }
    double mean = sd[0] / (double)Bsz;
    __syncthreads();
    sd[tid] = vq; __syncthreads();
    for (int s = 512; s > 0; s >>= 1) { if (tid < s) sd[tid] += sd[tid + s]; __syncthreads(); }
    double var = sd[0] / (double)Bsz - mean * mean;
    __syncthreads();
    sd[tid] = v5; __syncthreads();
    for (int s = 512; s > 0; s >>= 1) { if (tid < s) sd[tid] += sd[tid + s]; __syncthreads(); }
    float loss5 = (float)(sd[0] / (double)Bsz);
    __syncthreads();

    // order statistics 819 and 15563 (ranks 820/15564 derived below)
    unsigned *tot = (unsigned *)sd;
    unsigned k5  = radix_select(819,   ubuf, tot, selres);
    unsigned k95 = radix_select(15563, ubuf, tot, selres);

    // one pass: count(keys <= k) and min(keys > k) for both thresholds
    int *si = (int *)ubuf;
    unsigned *su = ubuf + 1024;
    int c5 = 0, c95 = 0;
    unsigned mg5 = 0xffffffffu, mg95 = 0xffffffffu;
    for (int i = tid; i < Bsz; i += 1024) {
        unsigned k = g_keys[i];
        if (k <= k5)  c5++;  else mg5  = min(mg5,  k);
        if (k <= k95) c95++; else mg95 = min(mg95, k);
    }
    si[tid] = c5; su[tid] = mg5; __syncthreads();
    for (int s = 512; s > 0; s >>= 1) {
        if (tid < s) { si[tid] += si[tid + s]; su[tid] = min(su[tid], su[tid + s]); }
        __syncthreads();
    }
    int cle5 = si[0]; unsigned mgt5 = su[0];
    __syncthreads();
    si[tid] = c95; su[tid] = mg95; __syncthreads();
    for (int s = 512; s > 0; s >>= 1) {
        if (tid < s) { si[tid] += si[tid + s]; su[tid] = min(su[tid], su[tid + s]); }
        __syncthreads();
    }
    int cle95 = si[0]; unsigned mgt95 = su[0];
    __syncthreads();

    float v819   = key_to_float(k5);
    float v820   = (820 < cle5) ? v819 : key_to_float(mgt5);
    float v15563 = key_to_float(k95);
    float v15564 = (15564 < cle95) ? v15563 : key_to_float(mgt95);
    const float f5  = 0.05f * 16383.0f - 819.0f;     // 0.15
    const float f95 = 0.95f * 16383.0f - 15563.0f;   // 0.85
    float p5  = v819   + f5  * (v820   - v819);
    float p95 = v15563 + f95 * (v15564 - v15563);

    // masked tail sums
    double slo = 0.0, shi = 0.0; int clo = 0, chi = 0;
    for (int i = tid; i < Bsz; i += 1024) {
        float xx = g_xfin[i];
        if (xx < p5)  { slo += (double)xx; clo++; }
        if (xx > p95) { shi += (double)xx; chi++; }
    }
    sd[tid] = slo; si[tid] = clo; __syncthreads();
    for (int s = 512; s > 0; s >>= 1) {
        if (tid < s) { sd[tid] += sd[tid + s]; si[tid] += si[tid + s]; }
        __syncthreads();
    }
    double sumlo = sd[0]; int cntlo = si[0];
    __syncthreads();
    sd[tid] = shi; si[tid] = chi; __syncthreads();
    for (int s = 512; s > 0; s >>= 1) {
        if (tid < s) { sd[tid] += sd[tid + s]; si[tid] += si[tid + s]; }
        __syncthreads();
    }
    double sumhi = sd[0]; int cnthi = si[0];

    if (tid == 0) {
        out[0] = (float)(-mean);
        out[1] = (float)var;
        out[2] = (float)(-sumlo / (double)(cntlo > 1 ? cntlo : 1));
        out[3] = (float)(-sumhi / (double)(cnthi > 1 ? cnthi : 1));
        out[4] = loss5;
        out[5] = g_stats[42];
        out[6] = g_stats[40];
    }
}

// ---------------- launcher ----------------
extern "C" void kernel_launch(void* const* d_in, const int* in_sizes, int n_in,
                              void* d_out, int out_size)
{
    const float* x_in  = (const float*)d_in[0];
    const float* S0    = (const float*)d_in[1];
    const float* dW    = (const float*)d_in[2];
    const float* u0W   = (const float*)d_in[3];
    const float* u0b   = (const float*)d_in[4];
    const float* uWin  = (const float*)d_in[5];
    const float* uWh   = (const float*)d_in[6];
    const float* ubh   = (const float*)d_in[7];
    const float* bng   = (const float*)d_in[8];
    const float* bnb   = (const float*)d_in[9];
    const float* uWout = (const float*)d_in[10];
    const float* ubout = (const float*)d_in[11];
    const float* optW  = (const float*)d_in[12];
    const float* optb  = (const float*)d_in[13];
    const float* KW    = (const float*)d_in[14];
    const float* Kb    = (const float*)d_in[15];

    k_prep  <<<128, 128>>>(x_in, optW, optb, KW, Kb);
    k_sim   <<<256, 128>>>(x_in, S0, dW, u0W, u0b, uWin, uWh, ubh, bng, bnb, uWout, ubout);
    k_reduce<<<160, 256>>>();
    k_fin   <<<1,   256>>>();
    k_path  <<<128, 128>>>();
    k_loss  <<<1,  1024>>>((float*)d_out);
}

// round 10
// speedup vs baseline: 1.7975x; 1.3456x over previous
#include <cuda_runtime.h>
#include <math.h>

#define Bsz 16384
#define Dn  20
#define NSTEP 100

// ---------------- device scratch (no allocation allowed) ----------------
__device__ float    g_ST [2 * Dn * Bsz]; // [0..19]: S transposed [d][b]
__device__ float    g_SQT[Dn * Bsz];     // S_Q transposed [d][b]
__device__ float    g_KT [2 * Dn * Bsz]; // strikes transposed: [d][b] calls, [20+d][b] puts
__device__ float    g_wT [2 * Dn * Bsz]; // softmax option weights transposed
__device__ float    g_xpre[Bsz];
__device__ float    g_dacc[Bsz];
__device__ float    g_xfin[Bsz];
__device__ float    g_stats[48];         // [0..19]=1/C0, [20..39]=1/P0, [40]=rescale, [42]=loss6
__device__ float    g_pA[128];           // alpha_tot partials
__device__ float    g_part5[128];        // per-block partials of C_T[:,0]
__device__ double   g_partM[128];        // per-block sum(x)
__device__ double   g_partQ[128];        // per-block sum(x^2)
__device__ unsigned g_keys[Bsz];

// ---------------- packed fp32x2 helpers ----------------
__device__ __forceinline__ unsigned long long pack2(float lo, float hi) {
    unsigned long long r; asm("mov.b64 %0,{%1,%2};" : "=l"(r) : "f"(lo), "f"(hi)); return r;
}
__device__ __forceinline__ void unpack2(unsigned long long v, float &lo, float &hi) {
    asm("mov.b64 {%0,%1},%2;" : "=f"(lo), "=f"(hi) : "l"(v));
}
__device__ __forceinline__ unsigned long long ffma2(unsigned long long a,
                                                    unsigned long long b,
                                                    unsigned long long c) {
    unsigned long long d;
    asm("fma.rn.f32x2 %0,%1,%2,%3;" : "=l"(d) : "l"(a), "l"(b), "l"(c));
    return d;
}

// Block-cooperative 64x64 dense layer over 64 paths.
// Hin/Hout: [64 units][64 paths] in smem. W: [k][j] 64x64 in smem.
// Thread (ug,pg) computes units ug*8..+8 x paths pg*4..+4.
// Unit-pairs packed in f32x2 (adjacent units come packed straight from W loads).
__device__ __forceinline__ void dense_gemm(const float *__restrict__ Hin,
                                           float *__restrict__ Hout,
                                           const float *__restrict__ W,
                                           const float *__restrict__ bias,
                                           const float *__restrict__ g,
                                           const float *__restrict__ bb,
                                           int ug, int pg)
{
    unsigned long long acc[16];   // [up 0..3][p 0..3]
    const float2 *bp = (const float2 *)(bias + ug * 8);
#pragma unroll
    for (int up = 0; up < 4; up++) {
        float2 b2 = bp[up];
        unsigned long long bv = pack2(b2.x, b2.y);
        acc[up*4+0] = bv; acc[up*4+1] = bv; acc[up*4+2] = bv; acc[up*4+3] = bv;
    }
#pragma unroll
    for (int k = 0; k < 64; k++) {
        const float4 hv = *(const float4 *)(Hin + k * 64 + pg * 4);
        unsigned long long h0 = pack2(hv.x, hv.x);
        unsigned long long h1 = pack2(hv.y, hv.y);
        unsigned long long h2 = pack2(hv.z, hv.z);
        unsigned long long h3 = pack2(hv.w, hv.w);
        const ulonglong2 *wp = (const ulonglong2 *)(W + k * 64 + ug * 8);
        ulonglong2 wa = wp[0], wb = wp[1];
        acc[0]  = ffma2(h0, wa.x, acc[0]);  acc[1]  = ffma2(h1, wa.x, acc[1]);
        acc[2]  = ffma2(h2, wa.x, acc[2]);  acc[3]  = ffma2(h3, wa.x, acc[3]);
        acc[4]  = ffma2(h0, wa.y, acc[4]);  acc[5]  = ffma2(h1, wa.y, acc[5]);
        acc[6]  = ffma2(h2, wa.y, acc[6]);  acc[7]  = ffma2(h3, wa.y, acc[7]);
        acc[8]  = ffma2(h0, wb.x, acc[8]);  acc[9]  = ffma2(h1, wb.x, acc[9]);
        acc[10] = ffma2(h2, wb.x, acc[10]); acc[11] = ffma2(h3, wb.x, acc[11]);
        acc[12] = ffma2(h0, wb.y, acc[12]); acc[13] = ffma2(h1, wb.y, acc[13]);
        acc[14] = ffma2(h2, wb.y, acc[14]); acc[15] = ffma2(h3, wb.y, acc[15]);
    }
#pragma unroll
    for (int up = 0; up < 4; up++) {
        float2 g2 = *(const float2 *)(g  + ug * 8 + up * 2);
        float2 q2 = *(const float2 *)(bb + ug * 8 + up * 2);
        int j0 = ug * 8 + up * 2;
#pragma unroll
        for (int p = 0; p < 4; p++) {
            float lo, hi; unpack2(acc[up*4+p], lo, hi);
            Hout[j0 * 64 + pg * 4 + p]       = fmaf(fmaxf(lo, 0.f), g2.x, q2.x);
            Hout[(j0 + 1) * 64 + pg * 4 + p] = fmaf(fmaxf(hi, 0.f), g2.y, q2.y);
        }
    }
}

// ---------------- K0: strikes + softmax weights + alpha_tot partials ----------------
__global__ void __launch_bounds__(128)
k_prep(const float *__restrict__ x_in, const float *__restrict__ optW,
       const float *__restrict__ optb, const float *__restrict__ KW,
       const float *__restrict__ Kb)
{
    __shared__ float sA[128];
    const int tid = threadIdx.x;
    const int b   = blockIdx.x * 128 + tid;
    float xv = x_in[b];

    float l[41]; float m = -1e30f;
#pragma unroll
    for (int j = 0; j < 41; j++) { l[j] = fmaf(xv, optW[j], optb[j]); m = fmaxf(m, l[j]); }
    float ssum = 0.f;
#pragma unroll
    for (int j = 0; j < 41; j++) { l[j] = __expf(l[j] - m); ssum += l[j]; }
    float inv_s = 1.0f / ssum;
#pragma unroll
    for (int j = 0; j < 40; j++) g_wT[j * Bsz + b] = l[j] * inv_s;

#pragma unroll
    for (int j = 0; j < 40; j++)
        g_KT[j * Bsz + b] = fmaf(0.25f, tanhf(fmaf(xv, KW[j], Kb[j])), 1.0f);

    sA[tid] = 1.0f - l[40] * inv_s;
    __syncthreads();
    for (int s = 64; s > 0; s >>= 1) {
        if (tid < s) sA[tid] += sA[tid + s];
        __syncthreads();
    }
    if (tid == 0) g_pA[blockIdx.x] = sA[0];
}

// ---------------- K1: SDE (2 thr/path) + block-GEMM policy MLP ----------------
// dynamic smem layout (floats):
//   sW1 @0 (4096), sW2 @4096 (4096), sWo @8192 (1280), sWi @9472 (64),
//   sB0 @9536 sG0 @9600 sBB0 @9664, sB1 @9728 sG1 @9792 sBB1 @9856,
//   sB2 @9920 sG2 @9984 sBB2 @10048, sBo @10112 (32), sX @10144 (64),
//   sHa @10208 (4096), sHb @14304 (4096)  -> total 18400 floats = 73600 B
#define SMEM_FLOATS 18400

__global__ void __launch_bounds__(128)
k_sim(const float *__restrict__ x_in,  const float *__restrict__ S0,
      const float *__restrict__ dW,    const float *__restrict__ u0W,
      const float *__restrict__ u0b,   const float *__restrict__ uWin,
      const float *__restrict__ uWh,   const float *__restrict__ ubh,
      const float *__restrict__ bng,   const float *__restrict__ bnb,
      const float *__restrict__ uWout, const float *__restrict__ ubout)
{
    extern __shared__ __align__(16) float sm[];
    float *sW1 = sm,         *sW2 = sm + 4096, *sWo = sm + 8192;
    float *sWi = sm + 9472,  *sB0 = sm + 9536, *sG0 = sm + 9600, *sBB0 = sm + 9664;
    float *sB1 = sm + 9728,  *sG1 = sm + 9792, *sBB1 = sm + 9856;
    float *sB2 = sm + 9920,  *sG2 = sm + 9984, *sBB2 = sm + 10048, *sBo = sm + 10112;
    float *sX  = sm + 10144, *sHa = sm + 10208, *sHb = sm + 14304;

    const int tid   = threadIdx.x;
    const int lpath = tid >> 1;             // local path 0..63
    const int path  = blockIdx.x * 64 + lpath;
    const int s     = tid & 1;              // asset half
    const int ug    = tid >> 4;             // GEMM unit-group 0..7
    const int pg    = tid & 15;             // GEMM path-group 0..15

    const float sqh = 0.1f;
    const float SIG = 0.2f;
    const float cS  = (0.06f - 0.5f * 0.2f * 0.2f) * 0.01f;
    const float rh  = 0.02f * 0.01f;
    const float muh = 0.06f * 0.01f;
    const float inv_bn = 1.0f / sqrtf(1.0f + 1e-3f);
    const float fq  = expf(-0.04f);         // exp((R-MU)*T)

    float x = x_in[path];
    float S[10], Nm1[10], alpha[10];
    float dacc = 0.f;
#pragma unroll
    for (int d = 0; d < 10; d++) {
        int gd = s * 10 + d;
        S[d] = S0[path * Dn + gd];
        Nm1[d] = 0.f;
        alpha[d] = fmaf(x, u0W[gd], u0b[gd]);
    }

    float2 ld[5];
    {
        const float2 *p = (const float2 *)(dW + (size_t)path * Dn + s * 10);
#pragma unroll
        for (int i = 0; i < 5; i++) ld[i] = p[i];
    }

#pragma unroll 1
    for (int n = 1; n <= NSTEP; n++) {
        float dv[10];
#pragma unroll
        for (int i = 0; i < 5; i++) { dv[2*i] = ld[i].x; dv[2*i+1] = ld[i].y; }
        if (n < NSTEP) {
            const float2 *p = (const float2 *)(dW + (size_t)n * Bsz * Dn + (size_t)path * Dn + s * 10);
#pragma unroll
            for (int i = 0; i < 5; i++) ld[i] = p[i];
        }

        float su = 0.f, sus = 0.f;
#pragma unroll
        for (int d = 0; d < 10; d++) {
            float u  = alpha[d];
            float Np = __fdividef(u, S[d]);
            if (n > 1) dacc += fabsf(Np - Nm1[d]);
            Nm1[d] = Np;
            float sdw = SIG * (sqh * dv[d]);
            su  += u;
            sus  = fmaf(u, muh + sdw, sus);
            S[d] *= __expf(cS + sdw);
        }
        float su_o  = __shfl_xor_sync(0xffffffffu, su, 1);
        float sus_o = __shfl_xor_sync(0xffffffffu, sus, 1);
        float suT  = s ? (su_o + su)   : (su + su_o);
        float susT = s ? (sus_o + sus) : (sus + sus_o);
        x = fmaf(x - suT, rh, x) + susT;

        if ((n % 10) == 0 && n < NSTEP) {
            const int idx = n / 10 - 1;
            if (s == 0) sX[lpath] = x;
            __syncthreads();                       // sX ready + prior H consumers done
            {
                const float *ws = uWh + (size_t)idx * 2 * 64 * 64;
                for (int i = tid; i < 4096; i += 128) { sW1[i] = ws[i]; sW2[i] = ws[4096 + i]; }
                const float *wo = uWout + (size_t)idx * 64 * Dn;
                for (int i = tid; i < 64 * Dn; i += 128) sWo[i] = wo[i];
                const float *wi = uWin + idx * 64;
                const float *bh = ubh + idx * 192;
                const float *gg = bng + idx * 192;
                const float *bv = bnb + idx * 192;
                for (int i = tid; i < 64; i += 128) {
                    sWi[i] = wi[i];
                    sB0[i] = bh[i];            sB1[i] = bh[64 + i];            sB2[i] = bh[128 + i];
                    sG0[i] = inv_bn * gg[i];   sG1[i] = inv_bn * gg[64 + i];   sG2[i] = inv_bn * gg[128 + i];
                    sBB0[i] = bv[i];           sBB1[i] = bv[64 + i];           sBB2[i] = bv[128 + i];
                }
                if (tid < Dn) sBo[tid] = ubout[idx * Dn + tid];
            }
            __syncthreads();

            // input layer (GEMM-mapped): sHa[j][p] = bn(relu(x_p*Wi_j + b_j))
            {
                const float4 xv4 = *(const float4 *)(sX + pg * 4);
                float xv[4] = { xv4.x, xv4.y, xv4.z, xv4.w };
#pragma unroll
                for (int u = 0; u < 8; u++) {
                    int j = ug * 8 + u;
                    float wi = sWi[j], b0 = sB0[j], g0 = sG0[j], q0 = sBB0[j];
#pragma unroll
                    for (int p = 0; p < 4; p++)
                        sHa[j * 64 + pg * 4 + p] =
                            fmaf(fmaxf(fmaf(xv[p], wi, b0), 0.f), g0, q0);
                }
            }
            __syncthreads();
            dense_gemm(sHa, sHb, sW1, sB1, sG1, sBB1, ug, pg);
            __syncthreads();
            dense_gemm(sHb, sHa, sW2, sB2, sG2, sBB2, ug, pg);
            __syncthreads();

            // out layer (SDE-mapped): alpha[s*10..] from sHa[k][lpath]
            float acc[10];
            const float *bo = sBo + s * 10;
#pragma unroll
            for (int d = 0; d < 10; d++) acc[d] = bo[d];
#pragma unroll
            for (int k = 0; k < 64; k++) {
                float hj = sHa[k * 64 + lpath];
                const float2 *wr = (const float2 *)(sWo + k * Dn + s * 10);
                float2 a0 = wr[0], a1 = wr[1], a2 = wr[2], a3 = wr[3], a4 = wr[4];
                acc[0] = fmaf(hj, a0.x, acc[0]); acc[1] = fmaf(hj, a0.y, acc[1]);
                acc[2] = fmaf(hj, a1.x, acc[2]); acc[3] = fmaf(hj, a1.y, acc[3]);
                acc[4] = fmaf(hj, a2.x, acc[4]); acc[5] = fmaf(hj, a2.y, acc[5]);
                acc[6] = fmaf(hj, a3.x, acc[6]); acc[7] = fmaf(hj, a3.y, acc[7]);
                acc[8] = fmaf(hj, a4.x, acc[8]); acc[9] = fmaf(hj, a4.y, acc[9]);
            }
#pragma unroll
            for (int d = 0; d < 10; d++) alpha[d] = acc[d];
        }
    }

    float dacc_o = __shfl_xor_sync(0xffffffffu, dacc, 1);
    if (s == 0) {
        g_xpre[path] = x;
        g_dacc[path] = dacc + dacc_o;
    }
#pragma unroll
    for (int d = 0; d < 10; d++) {
        int gd = s * 10 + d;
        g_ST[gd * Bsz + path]  = S[d];
        g_SQT[gd * Bsz + path] = S[d] / S0[path * Dn + gd] * fq;
    }
}

// ---------------- K2: C0/P0 (blocks 0..19, full per-asset) + rescale (block 20) ----------------
__global__ void __launch_bounds__(256)
k_reduce()
{
    __shared__ float sA[256], sB[256];
    const int tid = threadIdx.x, blk = blockIdx.x;
    const float disc = expf(-0.02f);

    if (blk < Dn) {
        const int d = blk;
        const float *SQ = g_SQT + d * Bsz;
        const float *Kc = g_KT  + d * Bsz;
        const float *Kp = g_KT  + (Dn + d) * Bsz;
        float cq = 0.f, pq = 0.f;
#pragma unroll 4
        for (int b = tid; b < Bsz; b += 256) {
            float sq = SQ[b];
            cq += fmaxf(sq - Kc[b], 0.f);
            pq += fmaxf(Kp[b] - sq, 0.f);
        }
        sA[tid] = cq; sB[tid] = pq; __syncthreads();
        for (int s = 128; s > 0; s >>= 1) {
            if (tid < s) { sA[tid] += sA[tid + s]; sB[tid] += sB[tid + s]; }
            __syncthreads();
        }
        if (tid == 0) {
            g_stats[d]      = (float)Bsz / (disc * sA[0]);   // 1/C0
            g_stats[Dn + d] = (float)Bsz / (disc * sB[0]);   // 1/P0
        }
    } else {
        sA[tid] = (tid < 128) ? g_pA[tid] : 0.f;
        __syncthreads();
        for (int s = 128; s > 0; s >>= 1) {
            if (tid < s) sA[tid] += sA[tid + s];
            __syncthreads();
        }
        if (tid == 0) {
            g_stats[40] = 1.0f - sA[0] / (float)Bsz;   // rescale
            g_stats[42] = g_KT[Bsz + 0];               // loss6 = K[0,1]
        }
    }
}

// ---------------- K3: per-path payoff + keys + moment partials ----------------
__global__ void __launch_bounds__(128)
k_path()
{
    __shared__ float  s5[128];
    __shared__ double sdm[128], sdq[128];
    const int tid = threadIdx.x;
    const int b   = blockIdx.x * 128 + tid;

    float rescale = g_stats[40];
    float pay = 0.f, ct0 = 0.f;
#pragma unroll
    for (int d = 0; d < Dn; d++) {
        float Sv = g_ST[d * Bsz + b];
        float CT = fmaxf(Sv - g_KT[d * Bsz + b], 0.f) * g_stats[d];
        float PT = fmaxf(g_KT[(Dn + d) * Bsz + b] - Sv, 0.f) * g_stats[Dn + d];
        pay += g_wT[d * Bsz + b] * CT + g_wT[(Dn + d) * Bsz + b] * PT;
        if (d == 0) ct0 = CT;
    }
    float xf = rescale * g_xpre[b] - 0.005f * rescale * g_dacc[b] + pay;
    g_xfin[b] = xf;
    unsigned u = __float_as_uint(xf);
    g_keys[b] = (u & 0x80000000u) ? ~u : (u | 0x80000000u);

    s5[tid]  = ct0;
    sdm[tid] = (double)xf;
    sdq[tid] = (double)xf * (double)xf;
    __syncthreads();
    for (int s = 64; s > 0; s >>= 1) {
        if (tid < s) { s5[tid] += s5[tid + s]; sdm[tid] += sdm[tid + s]; sdq[tid] += sdq[tid + s]; }
        __syncthreads();
    }
    if (tid == 0) {
        g_part5[blockIdx.x] = s5[0];
        g_partM[blockIdx.x] = sdm[0];
        g_partQ[blockIdx.x] = sdq[0];
    }
}

// ---------------- K4: losses (single block, 1024 threads) ----------------
__device__ __forceinline__ float key_to_float(unsigned k) {
    unsigned u = (k & 0x80000000u) ? (k ^ 0x80000000u) : ~k;
    return __uint_as_float(u);
}

__device__ unsigned radix_select(int rank, unsigned *ubuf /*32x256*/,
                                 unsigned *tot /*256*/, unsigned *selres /*2*/)
{
    unsigned prefix = 0, mask = 0;
    int r = rank;
    const int tid = threadIdx.x;
    const int lane = tid & 31;
    const int w = tid >> 5;
    unsigned *mine = ubuf + w * 256;
    for (int shift = 24; shift >= 0; shift -= 8) {
#pragma unroll
        for (int i = 0; i < 8; i++) ubuf[i * 1024 + tid] = 0;
        __syncthreads();
        for (int i = tid; i < Bsz; i += 1024) {
            unsigned k = g_keys[i];
            unsigned bin = ((k & mask) == prefix) ? ((k >> shift) & 255u) : 256u;
            unsigned peers = __match_any_sync(0xffffffffu, bin);
            if (bin < 256u && lane == (__ffs(peers) - 1))
                mine[bin] += (unsigned)__popc(peers);   // warp-private: race-free
        }
        __syncthreads();
        if (tid < 256) {
            unsigned sum = 0;
#pragma unroll
            for (int ww = 0; ww < 32; ww++) sum += ubuf[ww * 256 + tid];
            tot[tid] = sum;
        }
        __syncthreads();
        if (tid < 32) {
            unsigned carry = 0;
#pragma unroll
            for (int c = 0; c < 8; c++) {
                unsigned v = tot[c * 32 + lane], orig = v;
#pragma unroll
                for (int o = 1; o < 32; o <<= 1) {
                    unsigned t = __shfl_up_sync(0xffffffffu, v, o);
                    if (lane >= o) v += t;
                }
                unsigned inc = v + carry, exc = inc - orig;
                if ((unsigned)r >= exc && (unsigned)r < inc) {
                    selres[0] = (unsigned)(c * 32 + lane);
                    selres[1] = (unsigned)r - exc;
                }
                carry += __shfl_sync(0xffffffffu, v, 31);
            }
        }
        __syncthreads();
        prefix |= selres[0] << shift;
        mask   |= 0xFFu << shift;
        r = (int)selres[1];
        __syncthreads();
    }
    return prefix;
}

__global__ void __launch_bounds__(1024)
k_loss(float *__restrict__ out)
{
    __shared__ double   sd[1024];      // aliased as tot[] during radix
    __shared__ unsigned ubuf[8192];    // warp hists / si / su
    __shared__ unsigned selres[2];
    const int tid = threadIdx.x;

    double vm = 0.0, vq = 0.0, v5 = 0.0;
    if (tid < 128) { vm = g_partM[tid]; vq = g_partQ[tid]; v5 = (double)g_part5[tid]; }
    sd[tid] = vm; __syncthreads();
    for (int s = 512; s > 0; s >>= 1) { if (tid < s) sd[tid] += sd[tid + s]; __syncthreads(); }
    double mean = sd[0] / (double)Bsz;
    __syncthreads();
    sd[tid] = vq; __syncthreads();
    for (int s = 512; s > 0; s >>= 1) { if (tid < s) sd[tid] += sd[tid + s]; __syncthreads(); }
    double var = sd[0] / (double)Bsz - mean * mean;
    __syncthreads();
    sd[tid] = v5; __syncthreads();
    for (int s = 512; s > 0; s >>= 1) { if (tid < s) sd[tid] += sd[tid + s]; __syncthreads(); }
    float loss5 = (float)(sd[0] / (double)Bsz);
    __syncthreads();

    unsigned *tot = (unsigned *)sd;
    unsigned k5  = radix_select(819,   ubuf, tot, selres);
    unsigned k95 = radix_select(15563, ubuf, tot, selres);

    int *si = (int *)ubuf;
    unsigned *su = ubuf + 1024;
    int c5 = 0, c95 = 0;
    unsigned mg5 = 0xffffffffu, mg95 = 0xffffffffu;
    for (int i = tid; i < Bsz; i += 1024) {
        unsigned k = g_keys[i];
        if (k <= k5)  c5++;  else mg5  = min(mg5,  k);
        if (k <= k95) c95++; else mg95 = min(mg95, k);
    }
    si[tid] = c5; su[tid] = mg5; __syncthreads();
    for (int s = 512; s > 0; s >>= 1) {
        if (tid < s) { si[tid] += si[tid + s]; su[tid] = min(su[tid], su[tid + s]); }
        __syncthreads();
    }
    int cle5 = si[0]; unsigned mgt5 = su[0];
    __syncthreads();
    si[tid] = c95; su[tid] = mg95; __syncthreads();
    for (int s = 512; s > 0; s >>= 1) {
        if (tid < s) { si[tid] += si[tid + s]; su[tid] = min(su[tid], su[tid + s]); }
        __syncthreads();
    }
    int cle95 = si[0]; unsigned mgt95 = su[0];
    __syncthreads();

    float v819   = key_to_float(k5);
    float v820   = (820 < cle5) ? v819 : key_to_float(mgt5);
    float v15563 = key_to_float(k95);
    float v15564 = (15564 < cle95) ? v15563 : key_to_float(mgt95);
    const float f5  = 0.05f * 16383.0f - 819.0f;     // 0.15
    const float f95 = 0.95f * 16383.0f - 15563.0f;   // 0.85
    float p5  = v819   + f5  * (v820   - v819);
    float p95 = v15563 + f95 * (v15564 - v15563);

    double slo = 0.0, shi = 0.0; int clo = 0, chi = 0;
    for (int i = tid; i < Bsz; i += 1024) {
        float xx = g_xfin[i];
        if (xx < p5)  { slo += (double)xx; clo++; }
        if (xx > p95) { shi += (double)xx; chi++; }
    }
    sd[tid] = slo; si[tid] = clo; __syncthreads();
    for (int s = 512; s > 0; s >>= 1) {
        if (tid < s) { sd[tid] += sd[tid + s]; si[tid] += si[tid + s]; }
        __syncthreads();
    }
    double sumlo = sd[0]; int cntlo = si[0];
    __syncthreads();
    sd[tid] = shi; si[tid] = chi; __syncthreads();
    for (int s = 512; s > 0; s >>= 1) {
        if (tid < s) { sd[tid] += sd[tid + s]; si[tid] += si[tid + s]; }
        __syncthreads();
    }
    double sumhi = sd[0]; int cnthi = si[0];

    if (tid == 0) {
        out[0] = (float)(-mean);
        out[1] = (float)var;
        out[2] = (float)(-sumlo / (double)(cntlo > 1 ? cntlo : 1));
        out[3] = (float)(-sumhi / (double)(cnthi > 1 ? cnthi : 1));
        out[4] = loss5;
        out[5] = g_stats[42];
        out[6] = g_stats[40];
    }
}

// ---------------- launcher ----------------
extern "C" void kernel_launch(void* const* d_in, const int* in_sizes, int n_in,
                              void* d_out, int out_size)
{
    const float* x_in  = (const float*)d_in[0];
    const float* S0    = (const float*)d_in[1];
    const float* dW    = (const float*)d_in[2];
    const float* u0W   = (const float*)d_in[3];
    const float* u0b   = (const float*)d_in[4];
    const float* uWin  = (const float*)d_in[5];
    const float* uWh   = (const float*)d_in[6];
    const float* ubh   = (const float*)d_in[7];
    const float* bng   = (const float*)d_in[8];
    const float* bnb   = (const float*)d_in[9];
    const float* uWout = (const float*)d_in[10];
    const float* ubout = (const float*)d_in[11];
    const float* optW  = (const float*)d_in[12];
    const float* optb  = (const float*)d_in[13];
    const float* KW    = (const float*)d_in[14];
    const float* Kb    = (const float*)d_in[15];

    const int smem_bytes = SMEM_FLOATS * 4;   // 73600 B > 48 KB default
    static int attr_set = 0;
    if (!attr_set) {
        cudaFuncSetAttribute(k_sim, cudaFuncAttributeMaxDynamicSharedMemorySize, smem_bytes);
        attr_set = 1;
    }

    k_prep  <<<128, 128>>>(x_in, optW, optb, KW, Kb);
    k_sim   <<<256, 128, smem_bytes>>>(x_in, S0, dW, u0W, u0b, uWin, uWh, ubh,
                                       bng, bnb, uWout, ubout);
    k_reduce<<<Dn + 1, 256>>>();
    k_path  <<<128, 128>>>();
    k_loss  <<<1, 1024>>>((float*)d_out);
}